// round 7
// baseline (speedup 1.0000x reference)
#include <cuda_runtime.h>
#include <cuda_fp16.h>
#include <math_constants.h>
#include <cstdint>

#define Nn 64
#define Ll 1024
#define Hh 1024

// ---------------------------------------------------------------------------
// Device scratch
// ---------------------------------------------------------------------------
__device__ float g_dhP[4][Nn * Hh];                   // dh partials (4 h-splits)
__device__ float g_scoreP[8][Nn * Ll];
__device__ __align__(16) __half g_Bh[Hh * Hh];        // Ws fp16
__device__ __align__(16) __half g_Eh[Nn * Ll * Hh];   // E fp16 (128 MB)
__device__ float4 g_ctxP4[4][Nn * (Hh / 4)];          // context partials

// ---------------------------------------------------------------------------
// Helpers
// ---------------------------------------------------------------------------
__device__ __forceinline__ uint32_t smem_u32(const void* p) {
    uint32_t a;
    asm("{ .reg .u64 t; cvta.to.shared.u64 t, %1; cvt.u32.u64 %0, t; }" : "=r"(a) : "l"(p));
    return a;
}
__device__ __forceinline__ float tanh_fast(float x) {
    float e = __expf(2.0f * x);
    return 1.0f - __fdividef(2.0f, e + 1.0f);
}
__device__ __forceinline__ void ldsm_x4(uint32_t* r, uint32_t addr) {
    asm volatile("ldmatrix.sync.aligned.m8n8.x4.shared.b16 {%0,%1,%2,%3}, [%4];"
                 : "=r"(r[0]), "=r"(r[1]), "=r"(r[2]), "=r"(r[3]) : "r"(addr));
}
__device__ __forceinline__ void mma_f16(float* c, const uint32_t* a, uint32_t b0, uint32_t b1) {
    asm volatile("mma.sync.aligned.m16n8k16.row.col.f32.f16.f16.f32 "
                 "{%0,%1,%2,%3}, {%4,%5,%6,%7}, {%8,%9}, {%0,%1,%2,%3};"
                 : "+f"(c[0]), "+f"(c[1]), "+f"(c[2]), "+f"(c[3])
                 : "r"(a[0]), "r"(a[1]), "r"(a[2]), "r"(a[3]), "r"(b0), "r"(b1));
}
__device__ __forceinline__ void cp_async16(uint32_t dst, const void* src) {
    asm volatile("cp.async.cg.shared.global [%0], [%1], 16;" :: "r"(dst), "l"(src) : "memory");
}
#define CP_COMMIT() asm volatile("cp.async.commit_group;" ::: "memory")

// 64B-row swizzle (verified): seg' = seg ^ ((row>>1)&3)
__device__ __forceinline__ uint32_t swz(int row, int seg) {
    return (uint32_t)(row * 64 + ((seg ^ ((row >> 1) & 3)) << 4));
}

// ---------------------------------------------------------------------------
// Convert Ws -> fp16
// ---------------------------------------------------------------------------
__global__ __launch_bounds__(256) void bconv_kernel(const float* __restrict__ Ws) {
    size_t i = (size_t)blockIdx.x * 256 + threadIdx.x;
    float4 w0 = ((const float4*)Ws)[2 * i];
    float4 w1 = ((const float4*)Ws)[2 * i + 1];
    __half2 h[4];
    h[0] = __floats2half2_rn(w0.x, w0.y);
    h[1] = __floats2half2_rn(w0.z, w0.w);
    h[2] = __floats2half2_rn(w1.x, w1.y);
    h[3] = __floats2half2_rn(w1.z, w1.w);
    ((uint4*)g_Bh)[i] = *(uint4*)h;
}

// ---------------------------------------------------------------------------
// Convert E -> fp16
// ---------------------------------------------------------------------------
__global__ __launch_bounds__(256) void econv_kernel(const float* __restrict__ E) {
    size_t i = (size_t)blockIdx.x * 256 + threadIdx.x;
    float4 w0 = ((const float4*)E)[2 * i];
    float4 w1 = ((const float4*)E)[2 * i + 1];
    __half2 h[4];
    h[0] = __floats2half2_rn(w0.x, w0.y);
    h[1] = __floats2half2_rn(w0.z, w0.w);
    h[2] = __floats2half2_rn(w1.x, w1.y);
    h[3] = __floats2half2_rn(w1.z, w1.w);
    ((uint4*)g_Eh)[i] = *(uint4*)h;
}

// ---------------------------------------------------------------------------
// dh partials: tiled GEMM, Wh read once. grid 64 = 16 k-blocks x 4 h-splits.
// ---------------------------------------------------------------------------
__global__ __launch_bounds__(256) void dh_kernel(const float* __restrict__ dec,
                                                 const float* __restrict__ Wh) {
    __shared__ float ds[64][68];   // [h-inner][n]
    __shared__ float ws[64][68];   // [h-inner][k]
    const int tid = threadIdx.x;
    const int kb = (blockIdx.x & 15) * 64;
    const int hs = blockIdx.x >> 4;
    const int n0 = (tid & 15) * 4;
    const int k0 = (tid >> 4) * 4;
    float acc[4][4] = {};
    for (int cc = 0; cc < 4; ++cc) {
        const int hb = hs * 256 + cc * 64;
        __syncthreads();
#pragma unroll
        for (int q = 0; q < 4; ++q) {
            int f4 = tid + 256 * q;
            int r = f4 >> 4;
            int col = f4 & 15;
            float4 a = *(const float4*)(dec + (size_t)r * Hh + hb + col * 4);
            ds[col * 4 + 0][r] = a.x; ds[col * 4 + 1][r] = a.y;
            ds[col * 4 + 2][r] = a.z; ds[col * 4 + 3][r] = a.w;
            float4 b = *(const float4*)(Wh + (size_t)(kb + r) * Hh + hb + col * 4);
            ws[col * 4 + 0][r] = b.x; ws[col * 4 + 1][r] = b.y;
            ws[col * 4 + 2][r] = b.z; ws[col * 4 + 3][r] = b.w;
        }
        __syncthreads();
#pragma unroll 8
        for (int h = 0; h < 64; ++h) {
            float a[4], b[4];
            *(float4*)a = *(const float4*)&ds[h][n0];
            *(float4*)b = *(const float4*)&ws[h][k0];
#pragma unroll
            for (int i = 0; i < 4; ++i)
#pragma unroll
                for (int j = 0; j < 4; ++j) acc[i][j] += a[i] * b[j];
        }
    }
#pragma unroll
    for (int i = 0; i < 4; ++i)
#pragma unroll
        for (int j = 0; j < 4; ++j)
            g_dhP[hs][(n0 + i) * Hh + kb + k0 + j] = acc[i][j];
}

// ---------------------------------------------------------------------------
// Fused score kernel: fp16 mma.sync GEMM + tanh(.)·v epilogue.
// CTA 128x128, 256 threads, 6-stage cp.async, 4 j-blocks, 2 CTAs/SM.
// B-ldsm software-prefetched between MMA batches.
// ---------------------------------------------------------------------------
#define A_BYTES 8192
#define STAGE_BYTES (2 * A_BYTES)
#define NSTAGE 6
#define SM_DH   0
#define SM_V    512
#define SM_SRED 1024
#define SM_STG  2048
#define SM_TOTAL (SM_STG + NSTAGE * STAGE_BYTES)  // 100352

__global__ __launch_bounds__(256, 2) void score_kernel(const float* __restrict__ v) {
    extern __shared__ char smem[];
    const uint32_t sb = smem_u32(smem);
    const int tid = threadIdx.x;
    const int lane = tid & 31;
    const int wid = tid >> 5;
    const int wm = wid & 3;
    const int wn = wid >> 2;
    const int row0 = blockIdx.x * 128;
    const int n = row0 >> 10;

    // loader indices
    const int l_row0 = tid >> 2, l_seg0 = tid & 3;
    const int l_row1 = (tid + 256) >> 2, l_seg1 = (tid + 256) & 3;
    const uint32_t l_dst0 = swz(l_row0, l_seg0);
    const uint32_t l_dst1 = swz(l_row1, l_seg1);
    const size_t gA0 = (size_t)(row0 + l_row0) * Hh + l_seg0 * 8;
    const size_t gA1 = (size_t)(row0 + l_row1) * Hh + l_seg1 * 8;

    // hoisted ldsm offsets: aoff[ks][mt], boff[ks][np]
    uint32_t aoff[2][2], boff[2][4];
    {
        const int a_seg0 = lane >> 4;
        const int b_seg0 = (lane >> 3) & 1;
#pragma unroll
        for (int ks = 0; ks < 2; ++ks) {
#pragma unroll
            for (int mt = 0; mt < 2; ++mt) {
                int r = wm * 32 + mt * 16 + (lane & 15);
                aoff[ks][mt] =
                    (uint32_t)(r * 64 + (((a_seg0 + ks * 2) ^ ((r >> 1) & 3)) << 4));
            }
#pragma unroll
            for (int np = 0; np < 4; ++np) {
                int r = wn * 64 + np * 16 + ((lane >> 4) << 3) + (lane & 7);
                boff[ks][np] =
                    (uint32_t)(r * 64 + (((b_seg0 + ks * 2) ^ ((r >> 1) & 3)) << 4));
            }
        }
    }

    for (int jj = 0; jj < 4; ++jj) {
        const int jblk = blockIdx.y * 4 + jj;
        const int jbase = jblk * 128;
        const size_t gB0 = (size_t)(jbase + l_row0) * Hh + l_seg0 * 8;
        const size_t gB1 = (size_t)(jbase + l_row1) * Hh + l_seg1 * 8;

        if (tid < 128) {
            int idx = (n << 10) + jbase + tid;
            ((float*)(smem + SM_DH))[tid] =
                g_dhP[0][idx] + g_dhP[1][idx] + g_dhP[2][idx] + g_dhP[3][idx];
            ((float*)(smem + SM_V))[tid] = v[jbase + tid];
        }
        __syncthreads();

        auto cp_stage = [&](int stg, int kb) {
            const uint32_t base = sb + SM_STG + (uint32_t)stg * STAGE_BYTES;
            cp_async16(base + l_dst0, g_Eh + gA0 + kb);
            cp_async16(base + l_dst1, g_Eh + gA1 + kb);
            cp_async16(base + A_BYTES + l_dst0, g_Bh + gB0 + kb);
            cp_async16(base + A_BYTES + l_dst1, g_Bh + gB1 + kb);
        };

        float acc[2][8][4];
#pragma unroll
        for (int mt = 0; mt < 2; ++mt)
#pragma unroll
            for (int nt = 0; nt < 8; ++nt)
#pragma unroll
                for (int e = 0; e < 4; ++e) acc[mt][nt][e] = 0.f;

#pragma unroll
        for (int s = 0; s < 5; ++s) {
            cp_stage(s, s * 32);
            CP_COMMIT();
        }

        for (int c = 0; c < 32; ++c) {
            const int pend = (31 - c) < 4 ? (31 - c) : 4;
            switch (pend) {
                case 4: asm volatile("cp.async.wait_group 4;" ::: "memory"); break;
                case 3: asm volatile("cp.async.wait_group 3;" ::: "memory"); break;
                case 2: asm volatile("cp.async.wait_group 2;" ::: "memory"); break;
                case 1: asm volatile("cp.async.wait_group 1;" ::: "memory"); break;
                default: asm volatile("cp.async.wait_group 0;" ::: "memory"); break;
            }
            __syncthreads();
            if (c + 5 < 32) {
                cp_stage((c + 5) % NSTAGE, (c + 5) * 32);
                CP_COMMIT();
            }

            const uint32_t base = sb + SM_STG + (uint32_t)(c % NSTAGE) * STAGE_BYTES;
            const uint32_t sA = base;
            const uint32_t sB = base + A_BYTES;

#pragma unroll
            for (int ks = 0; ks < 2; ++ks) {
                uint32_t ah[2][4];
                ldsm_x4(ah[0], sA + aoff[ks][0]);
                ldsm_x4(ah[1], sA + aoff[ks][1]);
                uint32_t bb[2][4];
                ldsm_x4(bb[0], sB + boff[ks][0]);
#pragma unroll
                for (int np = 0; np < 4; ++np) {
                    if (np < 3) ldsm_x4(bb[(np + 1) & 1], sB + boff[ks][np + 1]);
                    const uint32_t* bq = bb[np & 1];
                    mma_f16(acc[0][np * 2 + 0], ah[0], bq[0], bq[1]);
                    mma_f16(acc[0][np * 2 + 1], ah[0], bq[2], bq[3]);
                    mma_f16(acc[1][np * 2 + 0], ah[1], bq[0], bq[1]);
                    mma_f16(acc[1][np * 2 + 1], ah[1], bq[2], bq[3]);
                }
            }
        }

        // epilogue
        const float* dhs = (const float*)(smem + SM_DH);
        const float* vs = (const float*)(smem + SM_V);
        float part[4] = {0.f, 0.f, 0.f, 0.f};
#pragma unroll
        for (int mt = 0; mt < 2; ++mt)
#pragma unroll
            for (int nt = 0; nt < 8; ++nt)
#pragma unroll
                for (int e = 0; e < 4; ++e) {
                    int col = wn * 64 + nt * 8 + (lane & 3) * 2 + (e & 1);
                    part[mt * 2 + (e >> 1)] += tanh_fast(acc[mt][nt][e] + dhs[col]) * vs[col];
                }
#pragma unroll
        for (int p = 0; p < 4; ++p) {
            part[p] += __shfl_xor_sync(0xffffffffu, part[p], 1);
            part[p] += __shfl_xor_sync(0xffffffffu, part[p], 2);
        }
        float* sred = (float*)(smem + SM_SRED);
        if ((lane & 3) == 0) {
#pragma unroll
            for (int mt = 0; mt < 2; ++mt)
#pragma unroll
                for (int rr = 0; rr < 2; ++rr) {
                    int row = wm * 32 + mt * 16 + (lane >> 2) + rr * 8;
                    sred[row * 2 + wn] = part[mt * 2 + rr];
                }
        }
        __syncthreads();
        if (tid < 128) {
            g_scoreP[jblk][row0 + tid] = sred[tid * 2] + sred[tid * 2 + 1];
        }
        __syncthreads();
    }
}

// ---------------------------------------------------------------------------
// Masked softmax (sums 8 j-block partials)
// ---------------------------------------------------------------------------
__global__ __launch_bounds__(256) void softmax_kernel(const int* __restrict__ mask,
                                                      float* __restrict__ attn) {
    __shared__ float red[256];
    const int n = blockIdx.x;
    const int tid = threadIdx.x;

    float s[4];
    int msk[4];
    float lmax = -CUDART_INF_F;
#pragma unroll
    for (int q = 0; q < 4; ++q) {
        int l = tid + 256 * q;
        msk[q] = mask[n * Ll + l];
        float acc = 0.f;
#pragma unroll
        for (int p = 0; p < 8; ++p) acc += g_scoreP[p][n * Ll + l];
        s[q] = acc;
        if (!msk[q]) lmax = fmaxf(lmax, s[q]);
    }
    red[tid] = lmax;
    __syncthreads();
    for (int o = 128; o; o >>= 1) {
        if (tid < o) red[tid] = fmaxf(red[tid], red[tid + o]);
        __syncthreads();
    }
    const float mx = red[0];
    __syncthreads();

    float p[4];
    float lsum = 0.f;
#pragma unroll
    for (int q = 0; q < 4; ++q) {
        p[q] = msk[q] ? 0.f : __expf(s[q] - mx);
        lsum += p[q];
    }
    red[tid] = lsum;
    __syncthreads();
    for (int o = 128; o; o >>= 1) {
        if (tid < o) red[tid] += red[tid + o];
        __syncthreads();
    }
    const float inv = 1.0f / red[0];
#pragma unroll
    for (int q = 0; q < 4; ++q) attn[n * Ll + tid + 256 * q] = p[q] * inv;
}

// ---------------------------------------------------------------------------
// Context: reads fp16 E; one block per (n, L-quarter); 8 h per thread.
// ---------------------------------------------------------------------------
__global__ __launch_bounds__(128) void context_kernel(const float* __restrict__ attn) {
    __shared__ float sa[256];
    const int n = blockIdx.x, lc = blockIdx.y;
    const int tid = threadIdx.x;
    sa[tid] = attn[n * Ll + lc * 256 + tid];
    sa[tid + 128] = attn[n * Ll + lc * 256 + tid + 128];
    __syncthreads();

    const uint4* Ep = (const uint4*)(g_Eh + (size_t)n * Ll * Hh) +
                      (size_t)(lc * 256) * 128 + tid;
    float acc[8] = {};
#pragma unroll 4
    for (int l = 0; l < 256; ++l) {
        uint4 u = Ep[(size_t)l * 128];
        const __half2* h2 = (const __half2*)&u;
        float a = sa[l];
#pragma unroll
        for (int q = 0; q < 4; ++q) {
            float2 f = __half22float2(h2[q]);
            acc[q * 2 + 0] += a * f.x;
            acc[q * 2 + 1] += a * f.y;
        }
    }
    float4* dst = &g_ctxP4[lc][n * 256 + tid * 2];
    dst[0] = make_float4(acc[0], acc[1], acc[2], acc[3]);
    dst[1] = make_float4(acc[4], acc[5], acc[6], acc[7]);
}

__global__ __launch_bounds__(256) void ctx_reduce_kernel(float4* __restrict__ ctx4) {
    int i = blockIdx.x * 256 + threadIdx.x;
    float4 a = g_ctxP4[0][i], b = g_ctxP4[1][i], c = g_ctxP4[2][i], d = g_ctxP4[3][i];
    ctx4[i] = make_float4(a.x + b.x + c.x + d.x, a.y + b.y + c.y + d.y,
                          a.z + b.z + c.z + d.z, a.w + b.w + c.w + d.w);
}

// ---------------------------------------------------------------------------
extern "C" void kernel_launch(void* const* d_in, const int* in_sizes, int n_in,
                              void* d_out, int out_size) {
    const float* dec  = (const float*)d_in[0];
    const float* E    = (const float*)d_in[1];
    const int*   mask = (const int*)  d_in[2];
    const float* Wh   = (const float*)d_in[3];
    const float* Ws   = (const float*)d_in[4];
    const float* v    = (const float*)d_in[5];

    float* out  = (float*)d_out;
    float* ctx  = out;
    float* attn = out + Nn * Hh;

    cudaFuncSetAttribute(score_kernel, cudaFuncAttributeMaxDynamicSharedMemorySize, SM_TOTAL);

    bconv_kernel<<<(Hh * Hh / 8) / 256, 256>>>(Ws);
    econv_kernel<<<(Nn * Ll * Hh / 8) / 256, 256>>>(E);
    dh_kernel<<<64, 256>>>(dec, Wh);
    score_kernel<<<dim3((Nn * Ll) / 128, 2), 256, SM_TOTAL>>>(v);
    softmax_kernel<<<Nn, 256>>>(mask, attn);
    context_kernel<<<dim3(Nn, 4), 128>>>(attn);
    ctx_reduce_kernel<<<(Nn * Hh / 4) / 256, 256>>>((float4*)ctx);
}

// round 9
// speedup vs baseline: 1.0690x; 1.0690x over previous
#include <cuda_runtime.h>
#include <cuda_fp16.h>
#include <math_constants.h>
#include <cstdint>

#define Nn 64
#define Ll 1024
#define Hh 1024

// ---------------------------------------------------------------------------
// Device scratch
// ---------------------------------------------------------------------------
__device__ float g_dhP[4][Nn * Hh];
__device__ float g_scoreP[8][Nn * Ll];
__device__ __align__(16) __half g_Bh[Hh * Hh];
__device__ __align__(16) __half g_Eh[Nn * Ll * Hh];
__device__ float4 g_ctxP4[4][Nn * (Hh / 4)];

// ---------------------------------------------------------------------------
// Helpers
// ---------------------------------------------------------------------------
__device__ __forceinline__ uint32_t smem_u32(const void* p) {
    uint32_t a;
    asm("{ .reg .u64 t; cvta.to.shared.u64 t, %1; cvt.u32.u64 %0, t; }" : "=r"(a) : "l"(p));
    return a;
}
__device__ __forceinline__ float tanh_fast(float x) {
    float e = __expf(2.0f * x);
    return 1.0f - __fdividef(2.0f, e + 1.0f);
}
__device__ __forceinline__ void ldsm_x4(uint32_t* r, uint32_t addr) {
    asm volatile("ldmatrix.sync.aligned.m8n8.x4.shared.b16 {%0,%1,%2,%3}, [%4];"
                 : "=r"(r[0]), "=r"(r[1]), "=r"(r[2]), "=r"(r[3]) : "r"(addr));
}
__device__ __forceinline__ void mma_f16(float* c, const uint32_t* a, uint32_t b0, uint32_t b1) {
    asm volatile("mma.sync.aligned.m16n8k16.row.col.f32.f16.f16.f32 "
                 "{%0,%1,%2,%3}, {%4,%5,%6,%7}, {%8,%9}, {%0,%1,%2,%3};"
                 : "+f"(c[0]), "+f"(c[1]), "+f"(c[2]), "+f"(c[3])
                 : "r"(a[0]), "r"(a[1]), "r"(a[2]), "r"(a[3]), "r"(b0), "r"(b1));
}
__device__ __forceinline__ void cp_async16(uint32_t dst, const void* src) {
    asm volatile("cp.async.cg.shared.global [%0], [%1], 16;" :: "r"(dst), "l"(src) : "memory");
}
#define CP_COMMIT() asm volatile("cp.async.commit_group;" ::: "memory")

// ---------------------------------------------------------------------------
// Convert Ws -> fp16
// ---------------------------------------------------------------------------
__global__ __launch_bounds__(256) void bconv_kernel(const float* __restrict__ Ws) {
    size_t i = (size_t)blockIdx.x * 256 + threadIdx.x;
    float4 w0 = ((const float4*)Ws)[2 * i];
    float4 w1 = ((const float4*)Ws)[2 * i + 1];
    __half2 h[4];
    h[0] = __floats2half2_rn(w0.x, w0.y);
    h[1] = __floats2half2_rn(w0.z, w0.w);
    h[2] = __floats2half2_rn(w1.x, w1.y);
    h[3] = __floats2half2_rn(w1.z, w1.w);
    ((uint4*)g_Bh)[i] = *(uint4*)h;
}

// ---------------------------------------------------------------------------
// Convert E -> fp16
// ---------------------------------------------------------------------------
__global__ __launch_bounds__(256) void econv_kernel(const float* __restrict__ E) {
    size_t i = (size_t)blockIdx.x * 256 + threadIdx.x;
    float4 w0 = ((const float4*)E)[2 * i];
    float4 w1 = ((const float4*)E)[2 * i + 1];
    __half2 h[4];
    h[0] = __floats2half2_rn(w0.x, w0.y);
    h[1] = __floats2half2_rn(w0.z, w0.w);
    h[2] = __floats2half2_rn(w1.x, w1.y);
    h[3] = __floats2half2_rn(w1.z, w1.w);
    ((uint4*)g_Eh)[i] = *(uint4*)h;
}

// ---------------------------------------------------------------------------
// dh partials: tiled GEMM, Wh read once. grid 64 = 16 k-blocks x 4 h-splits.
// ---------------------------------------------------------------------------
__global__ __launch_bounds__(256) void dh_kernel(const float* __restrict__ dec,
                                                 const float* __restrict__ Wh) {
    __shared__ float ds[64][68];
    __shared__ float ws[64][68];
    const int tid = threadIdx.x;
    const int kb = (blockIdx.x & 15) * 64;
    const int hs = blockIdx.x >> 4;
    const int n0 = (tid & 15) * 4;
    const int k0 = (tid >> 4) * 4;
    float acc[4][4] = {};
    for (int cc = 0; cc < 4; ++cc) {
        const int hb = hs * 256 + cc * 64;
        __syncthreads();
#pragma unroll
        for (int q = 0; q < 4; ++q) {
            int f4 = tid + 256 * q;
            int r = f4 >> 4;
            int col = f4 & 15;
            float4 a = *(const float4*)(dec + (size_t)r * Hh + hb + col * 4);
            ds[col * 4 + 0][r] = a.x; ds[col * 4 + 1][r] = a.y;
            ds[col * 4 + 2][r] = a.z; ds[col * 4 + 3][r] = a.w;
            float4 b = *(const float4*)(Wh + (size_t)(kb + r) * Hh + hb + col * 4);
            ws[col * 4 + 0][r] = b.x; ws[col * 4 + 1][r] = b.y;
            ws[col * 4 + 2][r] = b.z; ws[col * 4 + 3][r] = b.w;
        }
        __syncthreads();
#pragma unroll 8
        for (int h = 0; h < 64; ++h) {
            float a[4], b[4];
            *(float4*)a = *(const float4*)&ds[h][n0];
            *(float4*)b = *(const float4*)&ws[h][k0];
#pragma unroll
            for (int i = 0; i < 4; ++i)
#pragma unroll
                for (int j = 0; j < 4; ++j) acc[i][j] += a[i] * b[j];
        }
    }
#pragma unroll
    for (int i = 0; i < 4; ++i)
#pragma unroll
        for (int j = 0; j < 4; ++j)
            g_dhP[hs][(n0 + i) * Hh + kb + k0 + j] = acc[i][j];
}

// ---------------------------------------------------------------------------
// Fused score kernel: fp16 mma.sync GEMM + tanh(.)·v epilogue.
// Continuous 64-chunk pipeline (64 k-els/chunk, 4 j-blocks per CTA),
// grid.y=2 covers all 8 j-blocks. NSTAGE=3, 2 CTAs/SM.
// ---------------------------------------------------------------------------
#define A_BYTES 16384             // 128 rows x 128B (64 fp16 k-els)
#define STAGE_BYTES (2 * A_BYTES) // 32768
#define NSTAGE 3
#define SM_DH   0                 // 2 x 512B (double-buffered per j)
#define SM_V    1024              // 2 x 512B
#define SM_SRED 2048              // 1024B
#define SM_STG  3072
#define SM_TOTAL (SM_STG + NSTAGE * STAGE_BYTES)  // 101376

__global__ __launch_bounds__(256, 2) void score_kernel(const float* __restrict__ v) {
    extern __shared__ char smem[];
    const uint32_t sb = smem_u32(smem);
    const int tid = threadIdx.x;
    const int lane = tid & 31;
    const int wid = tid >> 5;
    const int wm = wid & 3;
    const int wn = wid >> 2;
    const int row0 = blockIdx.x * 128;
    const int n = row0 >> 10;
    const int j0 = blockIdx.y * 4;          // first global j-block for this CTA

    // ---- loader precompute: 4 16B units per tile ----
    uint32_t ldst[4];
    size_t gaoff[4];
    uint32_t gboff_c[4];
#pragma unroll
    for (int t = 0; t < 4; ++t) {
        int u = tid + 256 * t;            // 0..1023
        int lrow = u >> 3, lseg = u & 7;
        ldst[t] = (uint32_t)(lrow * 128 + ((lseg ^ (lrow & 7)) << 4));
        gaoff[t] = (size_t)(row0 + lrow) * Hh + lseg * 8;
        gboff_c[t] = (uint32_t)(lrow * Hh + lseg * 8);
    }

    // ---- ldsm address bases (bit-split XOR identity) ----
    uint32_t abase[2], axr[2], bbase[4], bxr[4];
    {
        const int aseg0 = lane >> 4;
        const int bseg0 = (lane >> 3) & 1;
#pragma unroll
        for (int mt = 0; mt < 2; ++mt) {
            int r = wm * 32 + mt * 16 + (lane & 15);
            abase[mt] = (uint32_t)(r * 128 + ((aseg0 ^ (r & 1)) << 4));
            axr[mt] = (uint32_t)(r & 6);
        }
#pragma unroll
        for (int np = 0; np < 4; ++np) {
            int r = wn * 64 + np * 16 + ((lane >> 4) << 3) + (lane & 7);
            bbase[np] = (uint32_t)(r * 128 + ((bseg0 ^ (r & 1)) << 4));
            bxr[np] = (uint32_t)(r & 6);
        }
    }

    auto cp_stage = [&](int cc2) {
        const uint32_t base = sb + SM_STG + (uint32_t)(cc2 % NSTAGE) * STAGE_BYTES;
        const int kb = (cc2 & 15) * 64;
        const uint32_t jb = (uint32_t)((j0 + (cc2 >> 4)) * 128) * Hh;
#pragma unroll
        for (int t = 0; t < 4; ++t) cp_async16(base + ldst[t], g_Eh + gaoff[t] + kb);
#pragma unroll
        for (int t = 0; t < 4; ++t)
            cp_async16(base + A_BYTES + ldst[t], g_Bh + jb + gboff_c[t] + kb);
    };

    // dh/v for first j-block
    if (tid < 128) {
        int idx = (n << 10) + j0 * 128 + tid;
        ((float*)(smem + SM_DH))[tid] =
            g_dhP[0][idx] + g_dhP[1][idx] + g_dhP[2][idx] + g_dhP[3][idx];
        ((float*)(smem + SM_V))[tid] = v[j0 * 128 + tid];
    }
    __syncthreads();

    float acc[2][8][4];
#pragma unroll
    for (int mt = 0; mt < 2; ++mt)
#pragma unroll
        for (int nt = 0; nt < 8; ++nt)
#pragma unroll
            for (int e = 0; e < 4; ++e) acc[mt][nt][e] = 0.f;

    cp_stage(0);
    CP_COMMIT();
    cp_stage(1);
    CP_COMMIT();

    for (int cc = 0; cc < 64; ++cc) {
        if (cc < 63)
            asm volatile("cp.async.wait_group 1;" ::: "memory");
        else
            asm volatile("cp.async.wait_group 0;" ::: "memory");
        __syncthreads();
        if (cc + 2 < 64) {
            cp_stage(cc + 2);
            CP_COMMIT();
        }

        const uint32_t base = sb + SM_STG + (uint32_t)(cc % NSTAGE) * STAGE_BYTES;
        const uint32_t sA = base;
        const uint32_t sB = base + A_BYTES;

#pragma unroll
        for (int ks = 0; ks < 4; ++ks) {
            const uint32_t ksx = (uint32_t)(ks * 2);
            uint32_t ah[2][4];
            ldsm_x4(ah[0], sA + abase[0] + ((ksx ^ axr[0]) << 4));
            ldsm_x4(ah[1], sA + abase[1] + ((ksx ^ axr[1]) << 4));
            uint32_t bb[2][4];
            ldsm_x4(bb[0], sB + bbase[0] + ((ksx ^ bxr[0]) << 4));
#pragma unroll
            for (int np = 0; np < 4; ++np) {
                if (np < 3)
                    ldsm_x4(bb[(np + 1) & 1], sB + bbase[np + 1] + ((ksx ^ bxr[np + 1]) << 4));
                const uint32_t* bq = bb[np & 1];
                mma_f16(acc[0][np * 2 + 0], ah[0], bq[0], bq[1]);
                mma_f16(acc[0][np * 2 + 1], ah[0], bq[2], bq[3]);
                mma_f16(acc[1][np * 2 + 0], ah[1], bq[0], bq[1]);
                mma_f16(acc[1][np * 2 + 1], ah[1], bq[2], bq[3]);
            }
        }

        if ((cc & 15) == 15) {
            const int jloc = cc >> 4;            // 0..3
            const int jglob = j0 + jloc;
            const int jb1 = jloc & 1;
            // preload next j's dh/v into alternate buffer
            if (jloc < 3 && tid < 128) {
                int idx = (n << 10) + (jglob + 1) * 128 + tid;
                ((float*)(smem + SM_DH + (1 - jb1) * 512))[tid] =
                    g_dhP[0][idx] + g_dhP[1][idx] + g_dhP[2][idx] + g_dhP[3][idx];
                ((float*)(smem + SM_V + (1 - jb1) * 512))[tid] =
                    v[(jglob + 1) * 128 + tid];
            }
            const float* dhs = (const float*)(smem + SM_DH + jb1 * 512);
            const float* vs = (const float*)(smem + SM_V + jb1 * 512);
            float part[4] = {0.f, 0.f, 0.f, 0.f};
#pragma unroll
            for (int mt = 0; mt < 2; ++mt)
#pragma unroll
                for (int nt = 0; nt < 8; ++nt)
#pragma unroll
                    for (int e = 0; e < 4; ++e) {
                        int col = wn * 64 + nt * 8 + (lane & 3) * 2 + (e & 1);
                        part[mt * 2 + (e >> 1)] +=
                            tanh_fast(acc[mt][nt][e] + dhs[col]) * vs[col];
                        acc[mt][nt][e] = 0.f;
                    }
#pragma unroll
            for (int p = 0; p < 4; ++p) {
                part[p] += __shfl_xor_sync(0xffffffffu, part[p], 1);
                part[p] += __shfl_xor_sync(0xffffffffu, part[p], 2);
            }
            float* sred = (float*)(smem + SM_SRED);
            if ((lane & 3) == 0) {
#pragma unroll
                for (int mt = 0; mt < 2; ++mt)
#pragma unroll
                    for (int rr = 0; rr < 2; ++rr) {
                        int row = wm * 32 + mt * 16 + (lane >> 2) + rr * 8;
                        sred[row * 2 + wn] = part[mt * 2 + rr];
                    }
            }
            __syncthreads();
            if (tid < 128)
                g_scoreP[jglob][row0 + tid] = sred[tid * 2] + sred[tid * 2 + 1];
            // next loop iteration's __syncthreads protects sred reuse
        }
    }
}

// ---------------------------------------------------------------------------
// Masked softmax (sums 8 j-block partials)
// ---------------------------------------------------------------------------
__global__ __launch_bounds__(256) void softmax_kernel(const int* __restrict__ mask,
                                                      float* __restrict__ attn) {
    __shared__ float red[256];
    const int n = blockIdx.x;
    const int tid = threadIdx.x;

    float s[4];
    int msk[4];
    float lmax = -CUDART_INF_F;
#pragma unroll
    for (int q = 0; q < 4; ++q) {
        int l = tid + 256 * q;
        msk[q] = mask[n * Ll + l];
        float acc = 0.f;
#pragma unroll
        for (int p = 0; p < 8; ++p) acc += g_scoreP[p][n * Ll + l];
        s[q] = acc;
        if (!msk[q]) lmax = fmaxf(lmax, s[q]);
    }
    red[tid] = lmax;
    __syncthreads();
    for (int o = 128; o; o >>= 1) {
        if (tid < o) red[tid] = fmaxf(red[tid], red[tid + o]);
        __syncthreads();
    }
    const float mx = red[0];
    __syncthreads();

    float p[4];
    float lsum = 0.f;
#pragma unroll
    for (int q = 0; q < 4; ++q) {
        p[q] = msk[q] ? 0.f : __expf(s[q] - mx);
        lsum += p[q];
    }
    red[tid] = lsum;
    __syncthreads();
    for (int o = 128; o; o >>= 1) {
        if (tid < o) red[tid] += red[tid + o];
        __syncthreads();
    }
    const float inv = 1.0f / red[0];
#pragma unroll
    for (int q = 0; q < 4; ++q) attn[n * Ll + tid + 256 * q] = p[q] * inv;
}

// ---------------------------------------------------------------------------
// Context (fp16 E) + reduce
// ---------------------------------------------------------------------------
__global__ __launch_bounds__(128) void context_kernel(const float* __restrict__ attn) {
    __shared__ float sa[256];
    const int n = blockIdx.x, lc = blockIdx.y;
    const int tid = threadIdx.x;
    sa[tid] = attn[n * Ll + lc * 256 + tid];
    sa[tid + 128] = attn[n * Ll + lc * 256 + tid + 128];
    __syncthreads();

    const uint4* Ep = (const uint4*)(g_Eh + (size_t)n * Ll * Hh) +
                      (size_t)(lc * 256) * 128 + tid;
    float acc[8] = {};
#pragma unroll 4
    for (int l = 0; l < 256; ++l) {
        uint4 u = Ep[(size_t)l * 128];
        const __half2* h2 = (const __half2*)&u;
        float a = sa[l];
#pragma unroll
        for (int q = 0; q < 4; ++q) {
            float2 f = __half22float2(h2[q]);
            acc[q * 2 + 0] += a * f.x;
            acc[q * 2 + 1] += a * f.y;
        }
    }
    float4* dst = &g_ctxP4[lc][n * 256 + tid * 2];
    dst[0] = make_float4(acc[0], acc[1], acc[2], acc[3]);
    dst[1] = make_float4(acc[4], acc[5], acc[6], acc[7]);
}

__global__ __launch_bounds__(256) void ctx_reduce_kernel(float4* __restrict__ ctx4) {
    int i = blockIdx.x * 256 + threadIdx.x;
    float4 a = g_ctxP4[0][i], b = g_ctxP4[1][i], c = g_ctxP4[2][i], d = g_ctxP4[3][i];
    ctx4[i] = make_float4(a.x + b.x + c.x + d.x, a.y + b.y + c.y + d.y,
                          a.z + b.z + c.z + d.z, a.w + b.w + c.w + d.w);
}

// ---------------------------------------------------------------------------
extern "C" void kernel_launch(void* const* d_in, const int* in_sizes, int n_in,
                              void* d_out, int out_size) {
    const float* dec  = (const float*)d_in[0];
    const float* E    = (const float*)d_in[1];
    const int*   mask = (const int*)  d_in[2];
    const float* Wh   = (const float*)d_in[3];
    const float* Ws   = (const float*)d_in[4];
    const float* v    = (const float*)d_in[5];

    float* out  = (float*)d_out;
    float* ctx  = out;
    float* attn = out + Nn * Hh;

    cudaFuncSetAttribute(score_kernel, cudaFuncAttributeMaxDynamicSharedMemorySize, SM_TOTAL);

    bconv_kernel<<<(Hh * Hh / 8) / 256, 256>>>(Ws);
    econv_kernel<<<(Nn * Ll * Hh / 8) / 256, 256>>>(E);
    dh_kernel<<<64, 256>>>(dec, Wh);
    score_kernel<<<dim3((Nn * Ll) / 128, 2), 256, SM_TOTAL>>>(v);
    softmax_kernel<<<Nn, 256>>>(mask, attn);
    context_kernel<<<dim3(Nn, 4), 128>>>(attn);
    ctx_reduce_kernel<<<(Nn * Hh / 4) / 256, 256>>>((float4*)ctx);
}